// round 2
// baseline (speedup 1.0000x reference)
#include <cuda_runtime.h>
#include <math.h>

#define D_DIM 512
#define BM 64
#define BN 128
#define BK 32
#define GAMMA 1.0f

// Scratch (allocation-free): squared norms
__device__ float g_fsq[8192];
__device__ float g_psq[4096];

// ---------------------------------------------------------------------------
// Kernel 1: squared norms of every feature row and prototype row.
// One warp per row.
// ---------------------------------------------------------------------------
__global__ void sqnorm_kernel(const float* __restrict__ feat,
                              const float* __restrict__ proto,
                              int B, int P) {
    int warp = (blockIdx.x * blockDim.x + threadIdx.x) >> 5;
    int lane = threadIdx.x & 31;
    if (warp >= B + P) return;
    const float* src;
    float* dst;
    if (warp < B) {
        src = feat + (size_t)warp * D_DIM;
        dst = &g_fsq[warp];
    } else {
        src = proto + (size_t)(warp - B) * D_DIM;
        dst = &g_psq[warp - B];
    }
    float s = 0.f;
#pragma unroll
    for (int t = 0; t < D_DIM / 32; t++) {
        float v = src[lane + 32 * t];
        s = fmaf(v, v, s);
    }
#pragma unroll
    for (int m = 16; m; m >>= 1) s += __shfl_xor_sync(0xffffffffu, s, m);
    if (lane == 0) *dst = s;
}

// ---------------------------------------------------------------------------
// Kernel 2: fused GEMM + TWO independent online logsumexps (den over all
// prototypes, num over same-class prototypes — separate running maxes so the
// numerator never underflows).
// Each CTA owns BM=64 feature rows, loops over P prototypes in BN=128 tiles.
// 256 threads, 4x8 microtile. ty=tid/16 owns 4 rows, tx=tid%16 owns 8 cols.
// Row reductions are 16-lane butterflies (ty constant across the 16 lanes).
// ---------------------------------------------------------------------------
__global__ __launch_bounds__(256, 1) void dce_kernel(
    const float* __restrict__ feat, const int* __restrict__ label,
    const float* __restrict__ proto, const int* __restrict__ plab,
    float* __restrict__ out, int B, int P) {
    __shared__ float As[BK][BM + 4];   // transposed: As[k][row]
    __shared__ float Bs[BK][BN + 4];   // transposed: Bs[k][col]
    __shared__ float psq_s[BN];
    __shared__ int pl_s[BN];

    const int tid = threadIdx.x;
    const int tx = tid & 15;
    const int ty = tid >> 4;
    const int row0 = blockIdx.x * BM;

    float m_den[4], s_den[4], m_num[4], s_num[4], fsq[4];
    int lab[4];
#pragma unroll
    for (int i = 0; i < 4; i++) {
        int r = row0 + ty * 4 + i;
        m_den[i] = -INFINITY;
        s_den[i] = 0.f;
        m_num[i] = -INFINITY;
        s_num[i] = 0.f;
        fsq[i] = g_fsq[r];
        lab[i] = label[r];
    }

    for (int pt = 0; pt < P; pt += BN) {
        __syncthreads();  // protect psq_s/pl_s from previous epilogue readers
        if (tid < BN) {
            psq_s[tid] = g_psq[pt + tid];
            pl_s[tid] = plab[pt + tid];
        }

        float acc[4][8];
#pragma unroll
        for (int i = 0; i < 4; i++)
#pragma unroll
            for (int j = 0; j < 8; j++) acc[i][j] = 0.f;

        for (int kt = 0; kt < D_DIM; kt += BK) {
            // Load A tile: 64 rows x 32 k-floats = 512 float4, 2 per thread
#pragma unroll
            for (int l = 0; l < 2; l++) {
                int q = tid + l * 256;
                int r = q >> 3;      // 8 float4 per row
                int c4 = q & 7;
                float4 v = *(const float4*)&feat[(size_t)(row0 + r) * D_DIM + kt + c4 * 4];
                As[c4 * 4 + 0][r] = v.x;
                As[c4 * 4 + 1][r] = v.y;
                As[c4 * 4 + 2][r] = v.z;
                As[c4 * 4 + 3][r] = v.w;
            }
            // Load B tile: 128 rows x 32 k-floats = 1024 float4, 4 per thread
#pragma unroll
            for (int l = 0; l < 4; l++) {
                int q = tid + l * 256;
                int r = q >> 3;
                int c4 = q & 7;
                float4 v = *(const float4*)&proto[(size_t)(pt + r) * D_DIM + kt + c4 * 4];
                Bs[c4 * 4 + 0][r] = v.x;
                Bs[c4 * 4 + 1][r] = v.y;
                Bs[c4 * 4 + 2][r] = v.z;
                Bs[c4 * 4 + 3][r] = v.w;
            }
            __syncthreads();
#pragma unroll
            for (int k = 0; k < BK; k++) {
                float a[4], b[8];
                *(float4*)a = *(const float4*)&As[k][ty * 4];
                *(float4*)&b[0] = *(const float4*)&Bs[k][tx * 8];
                *(float4*)&b[4] = *(const float4*)&Bs[k][tx * 8 + 4];
#pragma unroll
                for (int i = 0; i < 4; i++)
#pragma unroll
                    for (int j = 0; j < 8; j++)
                        acc[i][j] = fmaf(a[i], b[j], acc[i][j]);
            }
            __syncthreads();
        }

        // Epilogue: logits for this [64 x 128] tile; two online LSE updates.
#pragma unroll
        for (int i = 0; i < 4; i++) {
            float lg[8];
            bool same[8];
            float mxd = -INFINITY, mxn = -INFINITY;
#pragma unroll
            for (int j = 0; j < 8; j++) {
                int c = tx * 8 + j;
                float d2 = fsq[i] + psq_s[c] - 2.0f * acc[i][j];
                d2 = fmaxf(d2, 0.0f);
                lg[j] = -GAMMA * d2;
                same[j] = (pl_s[c] == lab[i]);
                mxd = fmaxf(mxd, lg[j]);
                if (same[j]) mxn = fmaxf(mxn, lg[j]);
            }
#pragma unroll
            for (int m = 8; m; m >>= 1) {
                mxd = fmaxf(mxd, __shfl_xor_sync(0xffffffffu, mxd, m));
                mxn = fmaxf(mxn, __shfl_xor_sync(0xffffffffu, mxn, m));
            }
            // --- denominator update (own max) ---
            float nmd = fmaxf(m_den[i], mxd);
            float pd = 0.f;
#pragma unroll
            for (int j = 0; j < 8; j++) pd += __expf(lg[j] - nmd);
#pragma unroll
            for (int m = 8; m; m >>= 1)
                pd += __shfl_xor_sync(0xffffffffu, pd, m);
            s_den[i] = fmaf(s_den[i], __expf(m_den[i] - nmd), pd);
            m_den[i] = nmd;
            // --- numerator update (separate max; avoids underflow) ---
            float nmn = fmaxf(m_num[i], mxn);
            float pn = 0.f;
#pragma unroll
            for (int j = 0; j < 8; j++)
                if (same[j]) pn += __expf(lg[j] - nmn);
#pragma unroll
            for (int m = 8; m; m >>= 1)
                pn += __shfl_xor_sync(0xffffffffu, pn, m);
            float scn = (m_num[i] == -INFINITY) ? 0.f : __expf(m_num[i] - nmn);
            s_num[i] = fmaf(s_num[i], scn, pn);
            m_num[i] = nmn;
        }
    }

    if (tx == 0) {
#pragma unroll
        for (int i = 0; i < 4; i++) {
            float ld = m_den[i] + logf(s_den[i]);
            float ln = m_num[i] + logf(s_num[i]);
            out[row0 + ty * 4 + i] = ld - ln;
        }
    }
}

// ---------------------------------------------------------------------------
// Launch
// ---------------------------------------------------------------------------
extern "C" void kernel_launch(void* const* d_in, const int* in_sizes, int n_in,
                              void* d_out, int out_size) {
    const float* feature = (const float*)d_in[0];
    const int* label = (const int*)d_in[1];
    const float* proto = (const float*)d_in[2];
    const int* plab = (const int*)d_in[3];
    float* out = (float*)d_out;

    int B = in_sizes[1];       // 8192
    int P = in_sizes[3];       // 4096

    int warps = B + P;
    int blocks1 = (warps * 32 + 255) / 256;
    sqnorm_kernel<<<blocks1, 256>>>(feature, proto, B, P);

    dce_kernel<<<B / BM, 256>>>(feature, label, proto, plab, out, B, P);
}

// round 4
// speedup vs baseline: 4.2158x; 4.2158x over previous
#include <cuda_runtime.h>
#include <cuda_fp16.h>
#include <math.h>
#include <stdint.h>

// ===========================================================================
// Problem constants
// ===========================================================================
#define B_ROWS 8192
#define P_ROWS 4096
#define D_DIM  512
#define NCHUNK (P_ROWS / 128)     // 32 column chunks of 128 protos

#define BM 128
#define BN 128
#define BK 32
#define KITERS (D_DIM / BK)       // 16
#define STAGES 3
#define STAGE_BYTES 32768          // A(hi|lo) 16KB + B(hi|lo) 16KB
#define OFF_PSQ  0                 // 128 floats
#define OFF_PLAB 512               // 128 ints
#define OFF_STAGE 1024
#define SMEM_TOTAL (OFF_STAGE + STAGES * STAGE_BYTES)   // 99328
#define CPITCH 132                 // epilogue C smem pitch (floats)

// ===========================================================================
// Scratch (allocation-free)
// ===========================================================================
__device__ __half g_Ahi[B_ROWS * D_DIM];
__device__ __half g_Alo[B_ROWS * D_DIM];
__device__ __half g_Bhi[P_ROWS * D_DIM];
__device__ __half g_Blo[P_ROWS * D_DIM];
__device__ float g_fsq[B_ROWS];
__device__ float g_psq[P_ROWS];
__device__ float g_pmd[NCHUNK * B_ROWS];
__device__ float g_psd[NCHUNK * B_ROWS];
__device__ float g_pmn[NCHUNK * B_ROWS];
__device__ float g_psn[NCHUNK * B_ROWS];

// ===========================================================================
// PTX helpers (base sm_103 features only: cp.async, ldmatrix, mma.sync)
// ===========================================================================
__device__ __forceinline__ uint32_t smem_u32(const void* p) {
    uint32_t a;
    asm("{ .reg .u64 t; cvta.to.shared.u64 t, %1; cvt.u32.u64 %0, t; }" : "=r"(a) : "l"(p));
    return a;
}
__device__ __forceinline__ void cp16(uint32_t dst, const void* src) {
    asm volatile("cp.async.cg.shared.global [%0], [%1], 16;" :: "r"(dst), "l"(src));
}
#define CP_COMMIT() asm volatile("cp.async.commit_group;" ::: "memory")
#define CP_WAIT(n)  asm volatile("cp.async.wait_group %0;" :: "n"(n) : "memory")

#define LDSM_X4(r0, r1, r2, r3, a)                                              \
    asm volatile("ldmatrix.sync.aligned.m8n8.x4.shared.b16 {%0,%1,%2,%3}, [%4];" \
        : "=r"(r0), "=r"(r1), "=r"(r2), "=r"(r3) : "r"(a))

#define MMA16816(c, a, b)                                                       \
    asm volatile("mma.sync.aligned.m16n8k16.row.col.f32.f16.f16.f32 "           \
        "{%0,%1,%2,%3}, {%4,%5,%6,%7}, {%8,%9}, {%0,%1,%2,%3};"                 \
        : "+f"((c)[0]), "+f"((c)[1]), "+f"((c)[2]), "+f"((c)[3])                \
        : "r"((a)[0]), "r"((a)[1]), "r"((a)[2]), "r"((a)[3]),                   \
          "r"((b)[0]), "r"((b)[1]))

// ===========================================================================
// Kernel 1: fp16 hi/lo split + squared norms. One warp per row.
// Row-major halves: g_?hi[row][512], g_?lo[row][512].
// ===========================================================================
__global__ void prep_kernel(const float* __restrict__ feat,
                            const float* __restrict__ proto) {
    int warp = (blockIdx.x * blockDim.x + threadIdx.x) >> 5;
    int lane = threadIdx.x & 31;
    if (warp >= B_ROWS + P_ROWS) return;
    bool isA = warp < B_ROWS;
    int row = isA ? warp : warp - B_ROWS;
    const float* src = (isA ? feat : proto) + (size_t)row * D_DIM;
    __half* dh = (isA ? g_Ahi : g_Bhi) + (size_t)row * D_DIM;
    __half* dl = (isA ? g_Alo : g_Blo) + (size_t)row * D_DIM;

    float s = 0.f;
#pragma unroll
    for (int t = 0; t < 4; t++) {
        int k = t * 128 + lane * 4;
        float4 v = *(const float4*)(src + k);
        s = fmaf(v.x, v.x, fmaf(v.y, v.y, fmaf(v.z, v.z, fmaf(v.w, v.w, s))));
        __align__(8) __half h[4], l[4];
        float x[4] = {v.x, v.y, v.z, v.w};
#pragma unroll
        for (int j = 0; j < 4; j++) {
            h[j] = __float2half_rn(x[j]);
            l[j] = __float2half_rn(x[j] - __half2float(h[j]));
        }
        *(uint2*)(dh + k) = *(uint2*)h;
        *(uint2*)(dl + k) = *(uint2*)l;
    }
#pragma unroll
    for (int m = 16; m; m >>= 1) s += __shfl_xor_sync(0xffffffffu, s, m);
    if (lane == 0) {
        if (isA) g_fsq[row] = s; else g_psq[row] = s;
    }
}

// ===========================================================================
// Kernel 2: fp16-split mma.sync GEMM + per-CTA dual online LSE partials.
// grid = (32 n-chunks, 64 m-tiles), 256 threads = 2(m) x 4(n) warps.
// SMEM tile rows pack hi|lo: 64 halves = 128B -> swizzle c ^ (r&7).
// ===========================================================================
__global__ __launch_bounds__(256, 1) void dce_mma_kernel(
    const int* __restrict__ label, const int* __restrict__ plab) {
    extern __shared__ __align__(1024) char smem[];
    float* psq_s = (float*)(smem + OFF_PSQ);
    int* plab_s = (int*)(smem + OFF_PLAB);
    char* stages = smem + OFF_STAGE;
    const uint32_t sb = smem_u32(stages);

    const int tid = threadIdx.x;
    const int lane = tid & 31;
    const int wid = tid >> 5;
    const int wm = wid >> 2;       // 0..1
    const int wn = wid & 3;        // 0..3
    const int m0 = blockIdx.y * BM;
    const int n0 = blockIdx.x * BN;

    if (tid < 128) {
        psq_s[tid] = g_psq[n0 + tid];
        plab_s[tid] = plab[n0 + tid];
    }

    float acc[4][4][4];
#pragma unroll
    for (int i = 0; i < 4; i++)
#pragma unroll
        for (int j = 0; j < 4; j++)
#pragma unroll
            for (int q = 0; q < 4; q++) acc[i][j][q] = 0.f;

    // --- stage loader: 8 x cp.async(16B) per thread per stage ---
    auto issue_stage = [&](int kt) {
        uint32_t base = sb + (kt % STAGES) * STAGE_BYTES;
#pragma unroll
        for (int j = 0; j < 4; j++) {
            int idx = tid + j * 256;            // 0..1023
            int r = idx >> 3;                   // 0..127
            int c = idx & 7;                    // 0..7 (0-3 = hi, 4-7 = lo)
            uint32_t so = (uint32_t)(r * 128 + ((c ^ (r & 7)) << 4));
            size_t koff = (size_t)kt * BK + (c & 3) * 8;
            const __half* srcA = (c < 4)
                ? g_Ahi + (size_t)(m0 + r) * D_DIM + koff
                : g_Alo + (size_t)(m0 + r) * D_DIM + koff;
            cp16(base + so, srcA);
            const __half* srcB = (c < 4)
                ? g_Bhi + (size_t)(n0 + r) * D_DIM + koff
                : g_Blo + (size_t)(n0 + r) * D_DIM + koff;
            cp16(base + 16384 + so, srcB);
        }
        CP_COMMIT();
    };

    issue_stage(0);
    issue_stage(1);

    for (int kt = 0; kt < KITERS; kt++) {
        CP_WAIT(1);
        __syncthreads();
        if (kt + 2 < KITERS) issue_stage(kt + 2);

        uint32_t base = sb + (kt % STAGES) * STAGE_BYTES;
#pragma unroll
        for (int ks = 0; ks < 2; ks++) {
            uint32_t Ah[4][4], Al[4][4], Bh[4][2], Bl[4][2];
            // A fragments: rows wm*64 + mt*16 + (lane&15), chunk split*4+ks*2+(lane>>4)
#pragma unroll
            for (int mt = 0; mt < 4; mt++) {
                int row = wm * 64 + mt * 16 + (lane & 15);
                int chh = 0 * 4 + ks * 2 + (lane >> 4);
                int chl = 1 * 4 + ks * 2 + (lane >> 4);
                uint32_t ah = base + row * 128 + ((chh ^ (row & 7)) << 4);
                uint32_t al = base + row * 128 + ((chl ^ (row & 7)) << 4);
                LDSM_X4(Ah[mt][0], Ah[mt][1], Ah[mt][2], Ah[mt][3], ah);
                LDSM_X4(Al[mt][0], Al[mt][1], Al[mt][2], Al[mt][3], al);
            }
            // B fragments: x4 covers an n-tile pair {2p, 2p+1}
#pragma unroll
            for (int p = 0; p < 2; p++) {
                int rn = wn * 32 + p * 16 + ((lane >> 4) << 3) + (lane & 7);
                int chh = 0 * 4 + ks * 2 + ((lane >> 3) & 1);
                int chl = 1 * 4 + ks * 2 + ((lane >> 3) & 1);
                uint32_t bh = base + 16384 + rn * 128 + ((chh ^ (rn & 7)) << 4);
                uint32_t bl = base + 16384 + rn * 128 + ((chl ^ (rn & 7)) << 4);
                LDSM_X4(Bh[2 * p][0], Bh[2 * p][1], Bh[2 * p + 1][0], Bh[2 * p + 1][1], bh);
                LDSM_X4(Bl[2 * p][0], Bl[2 * p][1], Bl[2 * p + 1][0], Bl[2 * p + 1][1], bl);
            }
#pragma unroll
            for (int mt = 0; mt < 4; mt++)
#pragma unroll
                for (int nt = 0; nt < 4; nt++) {
                    MMA16816(acc[mt][nt], Ah[mt], Bh[nt]);
                    MMA16816(acc[mt][nt], Ah[mt], Bl[nt]);
                    MMA16816(acc[mt][nt], Al[mt], Bh[nt]);
                }
        }
        __syncthreads();
    }

    CP_WAIT(0);
    __syncthreads();

    // --- dump accumulators to SMEM (reuse stage memory) ---
    float* Cs = (float*)stages;
#pragma unroll
    for (int mt = 0; mt < 4; mt++)
#pragma unroll
        for (int nt = 0; nt < 4; nt++) {
            int r = wm * 64 + mt * 16 + (lane >> 2);
            int c = wn * 32 + nt * 8 + ((lane & 3) << 1);
            Cs[r * CPITCH + c] = acc[mt][nt][0];
            Cs[r * CPITCH + c + 1] = acc[mt][nt][1];
            Cs[(r + 8) * CPITCH + c] = acc[mt][nt][2];
            Cs[(r + 8) * CPITCH + c + 1] = acc[mt][nt][3];
        }
    __syncthreads();

    // --- per-thread dual online LSE over 64 cols, pair-merge, write partials
    int row = tid >> 1;
    int c0 = (tid & 1) * 64;
    float fsq = g_fsq[m0 + row];
    int lab = label[m0 + row];
    float md = -INFINITY, mn = -INFINITY;
#pragma unroll 4
    for (int j = 0; j < 64; j++) {
        int col = c0 + j;
        float dot = Cs[row * CPITCH + col];
        float d2 = fmaxf(fsq + psq_s[col] - 2.0f * dot, 0.0f);
        float lg = -d2;
        Cs[row * CPITCH + col] = lg;
        md = fmaxf(md, lg);
        if (plab_s[col] == lab) mn = fmaxf(mn, lg);
    }
    float sd = 0.f, sn = 0.f;
#pragma unroll 4
    for (int j = 0; j < 64; j++) {
        int col = c0 + j;
        float lg = Cs[row * CPITCH + col];
        sd += __expf(lg - md);
        if (plab_s[col] == lab) sn += __expf(lg - mn);
    }
    // merge with partner thread (tid ^ 1, same warp)
    float md2 = __shfl_xor_sync(0xffffffffu, md, 1);
    float sd2 = __shfl_xor_sync(0xffffffffu, sd, 1);
    float mn2 = __shfl_xor_sync(0xffffffffu, mn, 1);
    float sn2 = __shfl_xor_sync(0xffffffffu, sn, 1);
    float M = fmaxf(md, md2);
    float SD = sd * __expf(md - M) + sd2 * __expf(md2 - M);
    float Mn = fmaxf(mn, mn2);
    float f0 = (mn == -INFINITY) ? 0.f : __expf(mn - Mn);
    float f1 = (mn2 == -INFINITY) ? 0.f : __expf(mn2 - Mn);
    float SN = sn * f0 + sn2 * f1;
    if ((tid & 1) == 0) {
        size_t o = (size_t)blockIdx.x * B_ROWS + m0 + row;
        g_pmd[o] = M;
        g_psd[o] = SD;
        g_pmn[o] = Mn;
        g_psn[o] = SN;
    }
}

// ===========================================================================
// Kernel 3: combine 32 chunk-partials per row -> loss.
// ===========================================================================
__global__ void combine_kernel(float* __restrict__ out) {
    int r = blockIdx.x * blockDim.x + threadIdx.x;
    if (r >= B_ROWS) return;
    float md = -INFINITY, sd = 0.f, mn = -INFINITY, sn = 0.f;
    for (int c = 0; c < NCHUNK; c++) {
        size_t o = (size_t)c * B_ROWS + r;
        float m2 = g_pmd[o], s2 = g_psd[o];
        float M = fmaxf(md, m2);
        sd = sd * __expf(md - M) + s2 * __expf(m2 - M);
        md = M;
        float mn2 = g_pmn[o], sn2 = g_psn[o];
        float Mn = fmaxf(mn, mn2);
        float f0 = (mn == -INFINITY) ? 0.f : __expf(mn - Mn);
        float f1 = (mn2 == -INFINITY) ? 0.f : __expf(mn2 - Mn);
        sn = sn * f0 + sn2 * f1;
        mn = Mn;
    }
    out[r] = (md + logf(sd)) - (mn + logf(sn));
}

// ===========================================================================
// Launch
// ===========================================================================
extern "C" void kernel_launch(void* const* d_in, const int* in_sizes, int n_in,
                              void* d_out, int out_size) {
    const float* feature = (const float*)d_in[0];
    const int* label = (const int*)d_in[1];
    const float* proto = (const float*)d_in[2];
    const int* plab = (const int*)d_in[3];
    float* out = (float*)d_out;

    cudaFuncSetAttribute(dce_mma_kernel, cudaFuncAttributeMaxDynamicSharedMemorySize,
                         SMEM_TOTAL);

    int warps = B_ROWS + P_ROWS;
    prep_kernel<<<(warps * 32 + 255) / 256, 256>>>(feature, proto);

    dim3 grid(P_ROWS / BN, B_ROWS / BM);
    dce_mma_kernel<<<grid, 256, SMEM_TOTAL>>>(label, plab);

    combine_kernel<<<(B_ROWS + 255) / 256, 256>>>(out);
}

// round 5
// speedup vs baseline: 4.9090x; 1.1644x over previous
#include <cuda_runtime.h>
#include <cuda_fp16.h>
#include <math.h>
#include <stdint.h>

// ===========================================================================
// Problem constants
// ===========================================================================
#define B_ROWS 8192
#define P_ROWS 4096
#define D_DIM  512
#define NCHUNK (P_ROWS / 128)     // 32 column chunks of 128 protos

#define BM 128
#define BN 128
#define BK 32
#define KITERS (D_DIM / BK)       // 16
#define STAGES 3
#define STAGE_BYTES 32768          // A(hi|lo) 16KB + B(hi|lo) 16KB
#define OFF_PSQ  0                 // 128 floats
#define OFF_PLAB 512               // 128 ints
#define OFF_STAGE 1024
#define SMEM_TOTAL (OFF_STAGE + STAGES * STAGE_BYTES)   // 99328 (2 CTAs/SM fit)
#define CPITCH 132                 // epilogue C smem pitch (floats)

// ===========================================================================
// Scratch (allocation-free)
// ===========================================================================
__device__ __half g_Ahi[B_ROWS * D_DIM];
__device__ __half g_Alo[B_ROWS * D_DIM];
__device__ __half g_Bhi[P_ROWS * D_DIM];
__device__ __half g_Blo[P_ROWS * D_DIM];
__device__ float g_fsq[B_ROWS];
__device__ float g_psq[P_ROWS];
__device__ float g_pmd[NCHUNK * B_ROWS];
__device__ float g_psd[NCHUNK * B_ROWS];
__device__ float g_pmn[NCHUNK * B_ROWS];
__device__ float g_psn[NCHUNK * B_ROWS];

// ===========================================================================
// PTX helpers (base sm_103 features only: cp.async, ldmatrix, mma.sync)
// ===========================================================================
__device__ __forceinline__ uint32_t smem_u32(const void* p) {
    uint32_t a;
    asm("{ .reg .u64 t; cvta.to.shared.u64 t, %1; cvt.u32.u64 %0, t; }" : "=r"(a) : "l"(p));
    return a;
}
__device__ __forceinline__ void cp16(uint32_t dst, const void* src) {
    asm volatile("cp.async.cg.shared.global [%0], [%1], 16;" :: "r"(dst), "l"(src));
}
#define CP_COMMIT() asm volatile("cp.async.commit_group;" ::: "memory")
#define CP_WAIT(n)  asm volatile("cp.async.wait_group %0;" :: "n"(n) : "memory")

#define LDSM_X4(r0, r1, r2, r3, a)                                              \
    asm volatile("ldmatrix.sync.aligned.m8n8.x4.shared.b16 {%0,%1,%2,%3}, [%4];" \
        : "=r"(r0), "=r"(r1), "=r"(r2), "=r"(r3) : "r"(a))

#define MMA16816(c, a, b)                                                       \
    asm volatile("mma.sync.aligned.m16n8k16.row.col.f32.f16.f16.f32 "           \
        "{%0,%1,%2,%3}, {%4,%5,%6,%7}, {%8,%9}, {%0,%1,%2,%3};"                 \
        : "+f"((c)[0]), "+f"((c)[1]), "+f"((c)[2]), "+f"((c)[3])                \
        : "r"((a)[0]), "r"((a)[1]), "r"((a)[2]), "r"((a)[3]),                   \
          "r"((b)[0]), "r"((b)[1]))

// ===========================================================================
// Kernel 1: fp16 hi/lo split + squared norms. One warp per row.
// ===========================================================================
__global__ void prep_kernel(const float* __restrict__ feat,
                            const float* __restrict__ proto) {
    int warp = (blockIdx.x * blockDim.x + threadIdx.x) >> 5;
    int lane = threadIdx.x & 31;
    if (warp >= B_ROWS + P_ROWS) return;
    bool isA = warp < B_ROWS;
    int row = isA ? warp : warp - B_ROWS;
    const float* src = (isA ? feat : proto) + (size_t)row * D_DIM;
    __half* dh = (isA ? g_Ahi : g_Bhi) + (size_t)row * D_DIM;
    __half* dl = (isA ? g_Alo : g_Blo) + (size_t)row * D_DIM;

    float s = 0.f;
#pragma unroll
    for (int t = 0; t < 4; t++) {
        int k = t * 128 + lane * 4;
        float4 v = *(const float4*)(src + k);
        s = fmaf(v.x, v.x, fmaf(v.y, v.y, fmaf(v.z, v.z, fmaf(v.w, v.w, s))));
        __align__(8) __half h[4], l[4];
        float x[4] = {v.x, v.y, v.z, v.w};
#pragma unroll
        for (int j = 0; j < 4; j++) {
            h[j] = __float2half_rn(x[j]);
            l[j] = __float2half_rn(x[j] - __half2float(h[j]));
        }
        *(uint2*)(dh + k) = *(uint2*)h;
        *(uint2*)(dl + k) = *(uint2*)l;
    }
#pragma unroll
    for (int m = 16; m; m >>= 1) s += __shfl_xor_sync(0xffffffffu, s, m);
    if (lane == 0) {
        if (isA) g_fsq[row] = s; else g_psq[row] = s;
    }
}

// ===========================================================================
// Kernel 2: fp16-split mma.sync GEMM + per-CTA dual online LSE partials.
// grid = (32 n-chunks, 64 m-tiles), 256 threads = 2(m) x 4(n) warps.
// __launch_bounds__(256, 2): 2 CTAs/SM so one CTA's MMAs cover the other's
// stage waits + epilogue. Inner loop restructured (B frags per ks, A frags
// per mt) to stay under the 128-reg occupancy-2 cap.
// ===========================================================================
__global__ __launch_bounds__(256, 2) void dce_mma_kernel(
    const int* __restrict__ label, const int* __restrict__ plab) {
    extern __shared__ __align__(1024) char smem[];
    float* psq_s = (float*)(smem + OFF_PSQ);
    int* plab_s = (int*)(smem + OFF_PLAB);
    char* stages = smem + OFF_STAGE;
    const uint32_t sb = smem_u32(stages);

    const int tid = threadIdx.x;
    const int lane = tid & 31;
    const int wid = tid >> 5;
    const int wm = wid >> 2;       // 0..1
    const int wn = wid & 3;        // 0..3
    const int m0 = blockIdx.y * BM;
    const int n0 = blockIdx.x * BN;

    if (tid < 128) {
        psq_s[tid] = g_psq[n0 + tid];
        plab_s[tid] = plab[n0 + tid];
    }

    float acc[4][4][4];
#pragma unroll
    for (int i = 0; i < 4; i++)
#pragma unroll
        for (int j = 0; j < 4; j++)
#pragma unroll
            for (int q = 0; q < 4; q++) acc[i][j][q] = 0.f;

    // --- stage loader: 8 x cp.async(16B) per thread per stage ---
    auto issue_stage = [&](int kt) {
        uint32_t base = sb + (kt % STAGES) * STAGE_BYTES;
#pragma unroll
        for (int j = 0; j < 4; j++) {
            int idx = tid + j * 256;            // 0..1023
            int r = idx >> 3;                   // 0..127
            int c = idx & 7;                    // 0..7 (0-3 = hi, 4-7 = lo)
            uint32_t so = (uint32_t)(r * 128 + ((c ^ (r & 7)) << 4));
            size_t koff = (size_t)kt * BK + (c & 3) * 8;
            const __half* srcA = (c < 4)
                ? g_Ahi + (size_t)(m0 + r) * D_DIM + koff
                : g_Alo + (size_t)(m0 + r) * D_DIM + koff;
            cp16(base + so, srcA);
            const __half* srcB = (c < 4)
                ? g_Bhi + (size_t)(n0 + r) * D_DIM + koff
                : g_Blo + (size_t)(n0 + r) * D_DIM + koff;
            cp16(base + 16384 + so, srcB);
        }
        CP_COMMIT();
    };

    issue_stage(0);
    issue_stage(1);

    for (int kt = 0; kt < KITERS; kt++) {
        CP_WAIT(1);
        __syncthreads();
        if (kt + 2 < KITERS) issue_stage(kt + 2);

        uint32_t base = sb + (kt % STAGES) * STAGE_BYTES;
#pragma unroll
        for (int ks = 0; ks < 2; ks++) {
            // B fragments for this k-16 slice (held across the mt loop)
            uint32_t Bh[4][2], Bl[4][2];
#pragma unroll
            for (int p = 0; p < 2; p++) {
                int rn = wn * 32 + p * 16 + ((lane >> 4) << 3) + (lane & 7);
                int chh = 0 * 4 + ks * 2 + ((lane >> 3) & 1);
                int chl = 1 * 4 + ks * 2 + ((lane >> 3) & 1);
                uint32_t bh = base + 16384 + rn * 128 + ((chh ^ (rn & 7)) << 4);
                uint32_t bl = base + 16384 + rn * 128 + ((chl ^ (rn & 7)) << 4);
                LDSM_X4(Bh[2 * p][0], Bh[2 * p][1], Bh[2 * p + 1][0], Bh[2 * p + 1][1], bh);
                LDSM_X4(Bl[2 * p][0], Bl[2 * p][1], Bl[2 * p + 1][0], Bl[2 * p + 1][1], bl);
            }
            // A fragments loaded per mt to keep register pressure low
#pragma unroll
            for (int mt = 0; mt < 4; mt++) {
                uint32_t Ah[4], Al[4];
                int row = wm * 64 + mt * 16 + (lane & 15);
                int chh = 0 * 4 + ks * 2 + (lane >> 4);
                int chl = 1 * 4 + ks * 2 + (lane >> 4);
                uint32_t ah = base + row * 128 + ((chh ^ (row & 7)) << 4);
                uint32_t al = base + row * 128 + ((chl ^ (row & 7)) << 4);
                LDSM_X4(Ah[0], Ah[1], Ah[2], Ah[3], ah);
                LDSM_X4(Al[0], Al[1], Al[2], Al[3], al);
#pragma unroll
                for (int nt = 0; nt < 4; nt++) {
                    MMA16816(acc[mt][nt], Ah, Bh[nt]);
                    MMA16816(acc[mt][nt], Ah, Bl[nt]);
                    MMA16816(acc[mt][nt], Al, Bh[nt]);
                }
            }
        }
        __syncthreads();
    }

    CP_WAIT(0);
    __syncthreads();

    // --- dump accumulators to SMEM (reuse stage memory) ---
    float* Cs = (float*)stages;
#pragma unroll
    for (int mt = 0; mt < 4; mt++)
#pragma unroll
        for (int nt = 0; nt < 4; nt++) {
            int r = wm * 64 + mt * 16 + (lane >> 2);
            int c = wn * 32 + nt * 8 + ((lane & 3) << 1);
            Cs[r * CPITCH + c] = acc[mt][nt][0];
            Cs[r * CPITCH + c + 1] = acc[mt][nt][1];
            Cs[(r + 8) * CPITCH + c] = acc[mt][nt][2];
            Cs[(r + 8) * CPITCH + c + 1] = acc[mt][nt][3];
        }
    __syncthreads();

    // --- per-thread dual online LSE over 64 cols, pair-merge, write partials
    int row = tid >> 1;
    int c0 = (tid & 1) * 64;
    float fsq = g_fsq[m0 + row];
    int lab = label[m0 + row];
    float md = -INFINITY, mn = -INFINITY;
#pragma unroll 4
    for (int j = 0; j < 64; j++) {
        int col = c0 + j;
        float dot = Cs[row * CPITCH + col];
        float d2 = fmaxf(fsq + psq_s[col] - 2.0f * dot, 0.0f);
        float lg = -d2;
        Cs[row * CPITCH + col] = lg;
        md = fmaxf(md, lg);
        if (plab_s[col] == lab) mn = fmaxf(mn, lg);
    }
    float sd = 0.f, sn = 0.f;
#pragma unroll 4
    for (int j = 0; j < 64; j++) {
        int col = c0 + j;
        float lg = Cs[row * CPITCH + col];
        sd += __expf(lg - md);
        if (plab_s[col] == lab) sn += __expf(lg - mn);
    }
    // merge with partner thread (tid ^ 1, same warp)
    float md2 = __shfl_xor_sync(0xffffffffu, md, 1);
    float sd2 = __shfl_xor_sync(0xffffffffu, sd, 1);
    float mn2 = __shfl_xor_sync(0xffffffffu, mn, 1);
    float sn2 = __shfl_xor_sync(0xffffffffu, sn, 1);
    float M = fmaxf(md, md2);
    float SD = sd * __expf(md - M) + sd2 * __expf(md2 - M);
    float Mn = fmaxf(mn, mn2);
    float f0 = (mn == -INFINITY) ? 0.f : __expf(mn - Mn);
    float f1 = (mn2 == -INFINITY) ? 0.f : __expf(mn2 - Mn);
    float SN = sn * f0 + sn2 * f1;
    if ((tid & 1) == 0) {
        size_t o = (size_t)blockIdx.x * B_ROWS + m0 + row;
        g_pmd[o] = M;
        g_psd[o] = SD;
        g_pmn[o] = Mn;
        g_psn[o] = SN;
    }
}

// ===========================================================================
// Kernel 3: combine 32 chunk-partials per row -> loss.
// ===========================================================================
__global__ void combine_kernel(float* __restrict__ out) {
    int r = blockIdx.x * blockDim.x + threadIdx.x;
    if (r >= B_ROWS) return;
    float md = -INFINITY, sd = 0.f, mn = -INFINITY, sn = 0.f;
    for (int c = 0; c < NCHUNK; c++) {
        size_t o = (size_t)c * B_ROWS + r;
        float m2 = g_pmd[o], s2 = g_psd[o];
        float M = fmaxf(md, m2);
        sd = sd * __expf(md - M) + s2 * __expf(m2 - M);
        md = M;
        float mn2 = g_pmn[o], sn2 = g_psn[o];
        float Mn = fmaxf(mn, mn2);
        float f0 = (mn == -INFINITY) ? 0.f : __expf(mn - Mn);
        float f1 = (mn2 == -INFINITY) ? 0.f : __expf(mn2 - Mn);
        sn = sn * f0 + sn2 * f1;
        mn = Mn;
    }
    out[r] = (md + logf(sd)) - (mn + logf(sn));
}

// ===========================================================================
// Launch
// ===========================================================================
extern "C" void kernel_launch(void* const* d_in, const int* in_sizes, int n_in,
                              void* d_out, int out_size) {
    const float* feature = (const float*)d_in[0];
    const int* label = (const int*)d_in[1];
    const float* proto = (const float*)d_in[2];
    const int* plab = (const int*)d_in[3];
    float* out = (float*)d_out;

    cudaFuncSetAttribute(dce_mma_kernel, cudaFuncAttributeMaxDynamicSharedMemorySize,
                         SMEM_TOTAL);

    int warps = B_ROWS + P_ROWS;
    prep_kernel<<<(warps * 32 + 255) / 256, 256>>>(feature, proto);

    dim3 grid(P_ROWS / BN, B_ROWS / BM);
    dce_mma_kernel<<<grid, 256, SMEM_TOTAL>>>(label, plab);

    combine_kernel<<<(B_ROWS + 255) / 256, 256>>>(out);
}

// round 6
// speedup vs baseline: 7.0309x; 1.4323x over previous
#include <cuda_runtime.h>
#include <cuda_fp16.h>
#include <math.h>
#include <stdint.h>

// ===========================================================================
// Problem constants
// ===========================================================================
#define B_ROWS 8192
#define P_ROWS 4096
#define D_DIM  512
#define NCHUNK (P_ROWS / 128)     // 32 column chunks of 128 protos

#define BM 128
#define BN 128
#define KITERS 16                  // 32-k iterations
#define NSUPER 8                   // 64-k superstages
#define SUPER_BYTES 49152          // A_hi(2kt) 16KB + B(kt0) 16KB + B(kt1) 16KB
#define OFF_PSQ  0                 // 128 floats
#define OFF_PLAB 512               // 128 ints
#define OFF_STAGE 1024
#define SMEM_TOTAL (OFF_STAGE + 2 * SUPER_BYTES)   // 99328 -> 2 CTAs/SM
#define CPITCH 132                 // epilogue C smem pitch (floats)

// ===========================================================================
// Scratch (allocation-free)
// ===========================================================================
__device__ __half g_Ahi[B_ROWS * D_DIM];
__device__ __half g_Bhi[P_ROWS * D_DIM];
__device__ __half g_Blo[P_ROWS * D_DIM];
__device__ float g_fsq[B_ROWS];
__device__ float g_psq[P_ROWS];
__device__ float g_pmd[NCHUNK * B_ROWS];
__device__ float g_psd[NCHUNK * B_ROWS];
__device__ float g_pmn[NCHUNK * B_ROWS];
__device__ float g_psn[NCHUNK * B_ROWS];

// ===========================================================================
// PTX helpers (base sm_103: cp.async, ldmatrix, mma.sync)
// ===========================================================================
__device__ __forceinline__ uint32_t smem_u32(const void* p) {
    uint32_t a;
    asm("{ .reg .u64 t; cvta.to.shared.u64 t, %1; cvt.u32.u64 %0, t; }" : "=r"(a) : "l"(p));
    return a;
}
__device__ __forceinline__ void cp16(uint32_t dst, const void* src) {
    asm volatile("cp.async.cg.shared.global [%0], [%1], 16;" :: "r"(dst), "l"(src));
}
#define CP_COMMIT() asm volatile("cp.async.commit_group;" ::: "memory")
#define CP_WAIT(n)  asm volatile("cp.async.wait_group %0;" :: "n"(n) : "memory")

#define LDSM_X4(r0, r1, r2, r3, a)                                              \
    asm volatile("ldmatrix.sync.aligned.m8n8.x4.shared.b16 {%0,%1,%2,%3}, [%4];" \
        : "=r"(r0), "=r"(r1), "=r"(r2), "=r"(r3) : "r"(a))

#define MMA16816(c, a, b)                                                       \
    asm volatile("mma.sync.aligned.m16n8k16.row.col.f32.f16.f16.f32 "           \
        "{%0,%1,%2,%3}, {%4,%5,%6,%7}, {%8,%9}, {%0,%1,%2,%3};"                 \
        : "+f"((c)[0]), "+f"((c)[1]), "+f"((c)[2]), "+f"((c)[3])                \
        : "r"((a)[0]), "r"((a)[1]), "r"((a)[2]), "r"((a)[3]),                   \
          "r"((b)[0]), "r"((b)[1]))

// ===========================================================================
// Kernel 1: fp16 hi/lo split + squared norms. One warp per row.
// A side: hi only. B side: hi + lo.
// ===========================================================================
__global__ void prep_kernel(const float* __restrict__ feat,
                            const float* __restrict__ proto) {
    int warp = (blockIdx.x * blockDim.x + threadIdx.x) >> 5;
    int lane = threadIdx.x & 31;
    if (warp >= B_ROWS + P_ROWS) return;
    bool isA = warp < B_ROWS;
    int row = isA ? warp : warp - B_ROWS;
    const float* src = (isA ? feat : proto) + (size_t)row * D_DIM;
    __half* dh = (isA ? g_Ahi : g_Bhi) + (size_t)row * D_DIM;
    __half* dl = isA ? (__half*)0 : g_Blo + (size_t)row * D_DIM;

    float s = 0.f;
#pragma unroll
    for (int t = 0; t < 4; t++) {
        int k = t * 128 + lane * 4;
        float4 v = *(const float4*)(src + k);
        s = fmaf(v.x, v.x, fmaf(v.y, v.y, fmaf(v.z, v.z, fmaf(v.w, v.w, s))));
        __align__(8) __half h[4], l[4];
        float x[4] = {v.x, v.y, v.z, v.w};
#pragma unroll
        for (int j = 0; j < 4; j++) {
            h[j] = __float2half_rn(x[j]);
            l[j] = __float2half_rn(x[j] - __half2float(h[j]));
        }
        *(uint2*)(dh + k) = *(uint2*)h;
        if (!isA) *(uint2*)(dl + k) = *(uint2*)l;
    }
#pragma unroll
    for (int m = 16; m; m >>= 1) s += __shfl_xor_sync(0xffffffffu, s, m);
    if (lane == 0) {
        if (isA) g_fsq[row] = s; else g_psq[row] = s;
    }
}

// ===========================================================================
// Kernel 2: 2-term fp16-split mma.sync GEMM + per-CTA dual online LSE.
// grid = (32 n-chunks, 64 m-tiles), 256 threads = 2(m) x 4(n) warps.
// Superstage (64-k): [A_hi rows 128B: chunks 0-3 = even kt, 4-7 = odd kt]
//                    [B(kt0): chunks 0-3 = hi, 4-7 = lo][B(kt1): same]
// Full 8-chunk XOR swizzle (c ^ (r&7)) -> conflict-free ldmatrix.
// ===========================================================================
__global__ __launch_bounds__(256, 2) void dce_mma_kernel(
    const int* __restrict__ label, const int* __restrict__ plab) {
    extern __shared__ __align__(1024) char smem[];
    float* psq_s = (float*)(smem + OFF_PSQ);
    int* plab_s = (int*)(smem + OFF_PLAB);
    char* stages = smem + OFF_STAGE;
    const uint32_t sb = smem_u32(stages);

    const int tid = threadIdx.x;
    const int lane = tid & 31;
    const int wid = tid >> 5;
    const int wm = wid >> 2;       // 0..1
    const int wn = wid & 3;        // 0..3
    const int m0 = blockIdx.y * BM;
    const int n0 = blockIdx.x * BN;

    if (tid < 128) {
        psq_s[tid] = g_psq[n0 + tid];
        plab_s[tid] = plab[n0 + tid];
    }

    float acc[4][4][4];
#pragma unroll
    for (int i = 0; i < 4; i++)
#pragma unroll
        for (int j = 0; j < 4; j++)
#pragma unroll
            for (int q = 0; q < 4; q++) acc[i][j][q] = 0.f;

    // --- superstage loader: 12 x cp.async(16B) per thread ---
    auto issue_super = [&](int s) {
        uint32_t base = sb + (s & 1) * SUPER_BYTES;
        int k0 = s * 64;
        // A_hi: 1024 x 16B. row r, chunk c: pe=c>>2, k = k0 + pe*32 + (c&3)*8
#pragma unroll
        for (int j = 0; j < 4; j++) {
            int idx = tid + j * 256;
            int r = idx >> 3;
            int c = idx & 7;
            uint32_t so = (uint32_t)(r * 128 + ((c ^ (r & 7)) << 4));
            cp16(base + so,
                 g_Ahi + (size_t)(m0 + r) * D_DIM + k0 + (c >> 2) * 32 + (c & 3) * 8);
        }
        // B blocks: for pe in {0,1}: row r, chunk c: c<4 hi else lo, k = k0+pe*32+(c&3)*8
#pragma unroll
        for (int j = 0; j < 8; j++) {
            int idx = tid + j * 256;            // 0..2047
            int pe = idx >> 10;
            int q = idx & 1023;
            int r = q >> 3;
            int c = q & 7;
            uint32_t so = (uint32_t)(16384 + pe * 16384 + r * 128 + ((c ^ (r & 7)) << 4));
            const __half* srcB = (c < 4)
                ? g_Bhi + (size_t)(n0 + r) * D_DIM + k0 + pe * 32 + c * 8
                : g_Blo + (size_t)(n0 + r) * D_DIM + k0 + pe * 32 + (c - 4) * 8;
            cp16(base + so, srcB);
        }
        CP_COMMIT();
    };

    issue_super(0);

    for (int s = 0; s < NSUPER; s++) {
        CP_WAIT(0);
        __syncthreads();           // data of s visible; all warps done reading s-1
        if (s + 1 < NSUPER) issue_super(s + 1);

        uint32_t base = sb + (s & 1) * SUPER_BYTES;
#pragma unroll
        for (int pe = 0; pe < 2; pe++) {
            uint32_t baseB = base + 16384 + pe * 16384;
#pragma unroll
            for (int ks = 0; ks < 2; ks++) {
                // B fragments (hi + lo) for this k-16 slice
                uint32_t Bh[4][2], Bl[4][2];
#pragma unroll
                for (int p = 0; p < 2; p++) {
                    int rn = wn * 32 + p * 16 + ((lane >> 4) << 3) + (lane & 7);
                    int chh = ks * 2 + ((lane >> 3) & 1);
                    int chl = 4 + ks * 2 + ((lane >> 3) & 1);
                    uint32_t bh = baseB + rn * 128 + ((chh ^ (rn & 7)) << 4);
                    uint32_t bl = baseB + rn * 128 + ((chl ^ (rn & 7)) << 4);
                    LDSM_X4(Bh[2 * p][0], Bh[2 * p][1], Bh[2 * p + 1][0], Bh[2 * p + 1][1], bh);
                    LDSM_X4(Bl[2 * p][0], Bl[2 * p][1], Bl[2 * p + 1][0], Bl[2 * p + 1][1], bl);
                }
                // A_hi fragments per mt
#pragma unroll
                for (int mt = 0; mt < 4; mt++) {
                    uint32_t Ah[4];
                    int row = wm * 64 + mt * 16 + (lane & 15);
                    int ch = pe * 4 + ks * 2 + (lane >> 4);
                    uint32_t ah = base + row * 128 + ((ch ^ (row & 7)) << 4);
                    LDSM_X4(Ah[0], Ah[1], Ah[2], Ah[3], ah);
#pragma unroll
                    for (int nt = 0; nt < 4; nt++) {
                        MMA16816(acc[mt][nt], Ah, Bh[nt]);
                        MMA16816(acc[mt][nt], Ah, Bl[nt]);
                    }
                }
            }
        }
    }

    __syncthreads();

    // --- dump accumulators to SMEM (reuse stage memory) ---
    float* Cs = (float*)stages;
#pragma unroll
    for (int mt = 0; mt < 4; mt++)
#pragma unroll
        for (int nt = 0; nt < 4; nt++) {
            int r = wm * 64 + mt * 16 + (lane >> 2);
            int c = wn * 32 + nt * 8 + ((lane & 3) << 1);
            Cs[r * CPITCH + c] = acc[mt][nt][0];
            Cs[r * CPITCH + c + 1] = acc[mt][nt][1];
            Cs[(r + 8) * CPITCH + c] = acc[mt][nt][2];
            Cs[(r + 8) * CPITCH + c + 1] = acc[mt][nt][3];
        }
    __syncthreads();

    // --- per-thread dual online LSE over 64 cols, pair-merge, write partials
    int row = tid >> 1;
    int c0 = (tid & 1) * 64;
    float fsq = g_fsq[m0 + row];
    int lab = label[m0 + row];
    float md = -INFINITY, mn = -INFINITY;
#pragma unroll 4
    for (int j = 0; j < 64; j++) {
        int col = c0 + j;
        float dot = Cs[row * CPITCH + col];
        float d2 = fmaxf(fsq + psq_s[col] - 2.0f * dot, 0.0f);
        float lg = -d2;
        Cs[row * CPITCH + col] = lg;
        md = fmaxf(md, lg);
        if (plab_s[col] == lab) mn = fmaxf(mn, lg);
    }
    float sd = 0.f, sn = 0.f;
#pragma unroll 4
    for (int j = 0; j < 64; j++) {
        int col = c0 + j;
        float lg = Cs[row * CPITCH + col];
        sd += __expf(lg - md);
        if (plab_s[col] == lab) sn += __expf(lg - mn);
    }
    // merge with partner thread (tid ^ 1, same warp)
    float md2 = __shfl_xor_sync(0xffffffffu, md, 1);
    float sd2 = __shfl_xor_sync(0xffffffffu, sd, 1);
    float mn2 = __shfl_xor_sync(0xffffffffu, mn, 1);
    float sn2 = __shfl_xor_sync(0xffffffffu, sn, 1);
    float M = fmaxf(md, md2);
    float SD = sd * __expf(md - M) + sd2 * __expf(md2 - M);
    float Mn = fmaxf(mn, mn2);
    float f0 = (mn == -INFINITY) ? 0.f : __expf(mn - Mn);
    float f1 = (mn2 == -INFINITY) ? 0.f : __expf(mn2 - Mn);
    float SN = sn * f0 + sn2 * f1;
    if ((tid & 1) == 0) {
        size_t o = (size_t)blockIdx.x * B_ROWS + m0 + row;
        g_pmd[o] = M;
        g_psd[o] = SD;
        g_pmn[o] = Mn;
        g_psn[o] = SN;
    }
}

// ===========================================================================
// Kernel 3: combine 32 chunk-partials per row -> loss.
// ===========================================================================
__global__ void combine_kernel(float* __restrict__ out) {
    int r = blockIdx.x * blockDim.x + threadIdx.x;
    if (r >= B_ROWS) return;
    float md = -INFINITY, sd = 0.f, mn = -INFINITY, sn = 0.f;
    for (int c = 0; c < NCHUNK; c++) {
        size_t o = (size_t)c * B_ROWS + r;
        float m2 = g_pmd[o], s2 = g_psd[o];
        float M = fmaxf(md, m2);
        sd = sd * __expf(md - M) + s2 * __expf(m2 - M);
        md = M;
        float mn2 = g_pmn[o], sn2 = g_psn[o];
        float Mn = fmaxf(mn, mn2);
        float f0 = (mn == -INFINITY) ? 0.f : __expf(mn - Mn);
        float f1 = (mn2 == -INFINITY) ? 0.f : __expf(mn2 - Mn);
        sn = sn * f0 + sn2 * f1;
        mn = Mn;
    }
    out[r] = (md + logf(sd)) - (mn + logf(sn));
}

// ===========================================================================
// Launch
// ===========================================================================
extern "C" void kernel_launch(void* const* d_in, const int* in_sizes, int n_in,
                              void* d_out, int out_size) {
    const float* feature = (const float*)d_in[0];
    const int* label = (const int*)d_in[1];
    const float* proto = (const float*)d_in[2];
    const int* plab = (const int*)d_in[3];
    float* out = (float*)d_out;

    cudaFuncSetAttribute(dce_mma_kernel, cudaFuncAttributeMaxDynamicSharedMemorySize,
                         SMEM_TOTAL);

    int warps = B_ROWS + P_ROWS;
    prep_kernel<<<(warps * 32 + 255) / 256, 256>>>(feature, proto);

    dim3 grid(P_ROWS / BN, B_ROWS / BM);
    dce_mma_kernel<<<grid, 256, SMEM_TOTAL>>>(label, plab);

    combine_kernel<<<(B_ROWS + 255) / 256, 256>>>(out);
}

// round 7
// speedup vs baseline: 7.0970x; 1.0094x over previous
#include <cuda_runtime.h>
#include <cuda_fp16.h>
#include <math.h>
#include <stdint.h>

// ===========================================================================
// Problem constants
// ===========================================================================
#define B_ROWS 8192
#define P_ROWS 4096
#define D_DIM  512
#define NCHUNK (P_ROWS / 128)     // 32 column chunks of 128 protos

#define BM 128
#define BN 128
#define KITERS 16                  // 32-k stages
#define NPIPE 4                    // pipeline depth
#define A_STAGE_BYTES 8192         // 128 rows x 64B (32-k of A_hi), SW64 swizzle
#define B_STAGE_BYTES 16384        // 128 rows x 128B (32-k of B hi|lo), SW128 swizzle
#define STAGE_BYTES (A_STAGE_BYTES + B_STAGE_BYTES)     // 24KB
#define OFF_PSQ  0                 // 128 floats
#define OFF_PLAB 512               // 128 ints
#define OFF_STAGE 1024
#define SMEM_TOTAL (OFF_STAGE + NPIPE * STAGE_BYTES)    // 99328 -> 2 CTAs/SM
#define CPITCH 132                 // epilogue C smem pitch (floats)

// ===========================================================================
// Scratch (allocation-free)
// ===========================================================================
__device__ __half g_Ahi[B_ROWS * D_DIM];
__device__ __half g_Bhi[P_ROWS * D_DIM];
__device__ __half g_Blo[P_ROWS * D_DIM];
__device__ float g_fsq[B_ROWS];
__device__ float g_psq[P_ROWS];
__device__ float g_pmd[NCHUNK * B_ROWS];
__device__ float g_psd[NCHUNK * B_ROWS];
__device__ float g_pmn[NCHUNK * B_ROWS];
__device__ float g_psn[NCHUNK * B_ROWS];

// ===========================================================================
// PTX helpers (base sm_103: cp.async, ldmatrix, mma.sync)
// ===========================================================================
__device__ __forceinline__ uint32_t smem_u32(const void* p) {
    uint32_t a;
    asm("{ .reg .u64 t; cvta.to.shared.u64 t, %1; cvt.u32.u64 %0, t; }" : "=r"(a) : "l"(p));
    return a;
}
__device__ __forceinline__ void cp16(uint32_t dst, const void* src) {
    asm volatile("cp.async.cg.shared.global [%0], [%1], 16;" :: "r"(dst), "l"(src));
}
#define CP_COMMIT() asm volatile("cp.async.commit_group;" ::: "memory")
#define CP_WAIT(n)  asm volatile("cp.async.wait_group %0;" :: "n"(n) : "memory")

#define LDSM_X4(r0, r1, r2, r3, a)                                              \
    asm volatile("ldmatrix.sync.aligned.m8n8.x4.shared.b16 {%0,%1,%2,%3}, [%4];" \
        : "=r"(r0), "=r"(r1), "=r"(r2), "=r"(r3) : "r"(a))

#define MMA16816(c, a, b)                                                       \
    asm volatile("mma.sync.aligned.m16n8k16.row.col.f32.f16.f16.f32 "           \
        "{%0,%1,%2,%3}, {%4,%5,%6,%7}, {%8,%9}, {%0,%1,%2,%3};"                 \
        : "+f"((c)[0]), "+f"((c)[1]), "+f"((c)[2]), "+f"((c)[3])                \
        : "r"((a)[0]), "r"((a)[1]), "r"((a)[2]), "r"((a)[3]),                   \
          "r"((b)[0]), "r"((b)[1]))

// ===========================================================================
// Kernel 1: fp16 hi/lo split + squared norms. One warp per row.
// A side: hi only. B side: hi + lo.
// ===========================================================================
__global__ void prep_kernel(const float* __restrict__ feat,
                            const float* __restrict__ proto) {
    int warp = (blockIdx.x * blockDim.x + threadIdx.x) >> 5;
    int lane = threadIdx.x & 31;
    if (warp >= B_ROWS + P_ROWS) return;
    bool isA = warp < B_ROWS;
    int row = isA ? warp : warp - B_ROWS;
    const float* src = (isA ? feat : proto) + (size_t)row * D_DIM;
    __half* dh = (isA ? g_Ahi : g_Bhi) + (size_t)row * D_DIM;
    __half* dl = isA ? (__half*)0 : g_Blo + (size_t)row * D_DIM;

    float s = 0.f;
#pragma unroll
    for (int t = 0; t < 4; t++) {
        int k = t * 128 + lane * 4;
        float4 v = *(const float4*)(src + k);
        s = fmaf(v.x, v.x, fmaf(v.y, v.y, fmaf(v.z, v.z, fmaf(v.w, v.w, s))));
        __align__(8) __half h[4], l[4];
        float x[4] = {v.x, v.y, v.z, v.w};
#pragma unroll
        for (int j = 0; j < 4; j++) {
            h[j] = __float2half_rn(x[j]);
            l[j] = __float2half_rn(x[j] - __half2float(h[j]));
        }
        *(uint2*)(dh + k) = *(uint2*)h;
        if (!isA) *(uint2*)(dl + k) = *(uint2*)l;
    }
#pragma unroll
    for (int m = 16; m; m >>= 1) s += __shfl_xor_sync(0xffffffffu, s, m);
    if (lane == 0) {
        if (isA) g_fsq[row] = s; else g_psq[row] = s;
    }
}

// ===========================================================================
// Kernel 2: 2-term fp16-split mma.sync GEMM, 4-deep cp.async pipeline,
// + per-CTA dual online LSE partials.
// grid = (32 n-chunks, 64 m-tiles), 256 threads = 2(m) x 4(n) warps.
// Stage (32-k, 24KB): A_hi 128x64B rows (chunks c^( (r>>1)&3 ), SW64-style,
// conflict-free ldmatrix) + B 128x128B rows (chunks 0-3 hi, 4-7 lo, SW128).
// ===========================================================================
__global__ __launch_bounds__(256, 2) void dce_mma_kernel(
    const int* __restrict__ label, const int* __restrict__ plab) {
    extern __shared__ __align__(1024) char smem[];
    float* psq_s = (float*)(smem + OFF_PSQ);
    int* plab_s = (int*)(smem + OFF_PLAB);
    char* stages = smem + OFF_STAGE;
    const uint32_t sb = smem_u32(stages);

    const int tid = threadIdx.x;
    const int lane = tid & 31;
    const int wid = tid >> 5;
    const int wm = wid >> 2;       // 0..1
    const int wn = wid & 3;        // 0..3
    const int m0 = blockIdx.y * BM;
    const int n0 = blockIdx.x * BN;

    if (tid < 128) {
        psq_s[tid] = g_psq[n0 + tid];
        plab_s[tid] = plab[n0 + tid];
    }

    float acc[4][4][4];
#pragma unroll
    for (int i = 0; i < 4; i++)
#pragma unroll
        for (int j = 0; j < 4; j++)
#pragma unroll
            for (int q = 0; q < 4; q++) acc[i][j][q] = 0.f;

    // --- stage loader: 6 x cp.async(16B) per thread (1536 chunks total) ---
    auto issue_stage = [&](int s) {
        uint32_t base = sb + (s & (NPIPE - 1)) * STAGE_BYTES;
        int k0 = s * 32;
        // A_hi: 512 chunks. row r (0..127), chunk c (0..3): k = k0 + c*8
#pragma unroll
        for (int j = 0; j < 2; j++) {
            int idx = tid + j * 256;
            int r = idx >> 2;
            int c = idx & 3;
            uint32_t so = (uint32_t)(r * 64 + ((c ^ ((r >> 1) & 3)) << 4));
            cp16(base + so, g_Ahi + (size_t)(m0 + r) * D_DIM + k0 + c * 8);
        }
        // B: 1024 chunks. row r, chunk c: c<4 -> hi k=k0+c*8, else lo k=k0+(c-4)*8
#pragma unroll
        for (int j = 0; j < 4; j++) {
            int idx = tid + j * 256;
            int r = idx >> 3;
            int c = idx & 7;
            uint32_t so = (uint32_t)(A_STAGE_BYTES + r * 128 + ((c ^ (r & 7)) << 4));
            const __half* srcB = (c < 4)
                ? g_Bhi + (size_t)(n0 + r) * D_DIM + k0 + c * 8
                : g_Blo + (size_t)(n0 + r) * D_DIM + k0 + (c - 4) * 8;
            cp16(base + so, srcB);
        }
        CP_COMMIT();
    };

    issue_stage(0);
    issue_stage(1);
    issue_stage(2);

    for (int s = 0; s < KITERS; s++) {
        CP_WAIT(2);                // stage s landed (2 newer groups may be in flight)
        __syncthreads();           // all warps done reading stage s-1 (buffer of s+3)
        if (s + 3 < KITERS) issue_stage(s + 3);

        uint32_t base = sb + (s & (NPIPE - 1)) * STAGE_BYTES;
        uint32_t baseB = base + A_STAGE_BYTES;
#pragma unroll
        for (int ks = 0; ks < 2; ks++) {
            // B fragments (hi + lo) for this k-16 slice
            uint32_t Bh[4][2], Bl[4][2];
#pragma unroll
            for (int p = 0; p < 2; p++) {
                int rn = wn * 32 + p * 16 + ((lane >> 4) << 3) + (lane & 7);
                int chh = ks * 2 + ((lane >> 3) & 1);
                int chl = 4 + chh;
                uint32_t bh = baseB + rn * 128 + ((chh ^ (rn & 7)) << 4);
                uint32_t bl = baseB + rn * 128 + ((chl ^ (rn & 7)) << 4);
                LDSM_X4(Bh[2 * p][0], Bh[2 * p][1], Bh[2 * p + 1][0], Bh[2 * p + 1][1], bh);
                LDSM_X4(Bl[2 * p][0], Bl[2 * p][1], Bl[2 * p + 1][0], Bl[2 * p + 1][1], bl);
            }
            // A_hi fragments per mt (SW64 swizzle on 64B rows)
#pragma unroll
            for (int mt = 0; mt < 4; mt++) {
                uint32_t Ah[4];
                int row = wm * 64 + mt * 16 + (lane & 15);
                int ch = ks * 2 + (lane >> 4);
                uint32_t ah = base + row * 64 + ((ch ^ ((row >> 1) & 3)) << 4);
                LDSM_X4(Ah[0], Ah[1], Ah[2], Ah[3], ah);
#pragma unroll
                for (int nt = 0; nt < 4; nt++) {
                    MMA16816(acc[mt][nt], Ah, Bh[nt]);
                    MMA16816(acc[mt][nt], Ah, Bl[nt]);
                }
            }
        }
    }

    CP_WAIT(0);
    __syncthreads();

    // --- dump accumulators to SMEM (reuse stage memory) ---
    float* Cs = (float*)stages;
#pragma unroll
    for (int mt = 0; mt < 4; mt++)
#pragma unroll
        for (int nt = 0; nt < 4; nt++) {
            int r = wm * 64 + mt * 16 + (lane >> 2);
            int c = wn * 32 + nt * 8 + ((lane & 3) << 1);
            Cs[r * CPITCH + c] = acc[mt][nt][0];
            Cs[r * CPITCH + c + 1] = acc[mt][nt][1];
            Cs[(r + 8) * CPITCH + c] = acc[mt][nt][2];
            Cs[(r + 8) * CPITCH + c + 1] = acc[mt][nt][3];
        }
    __syncthreads();

    // --- per-thread dual online LSE over 64 cols, pair-merge, write partials
    int row = tid >> 1;
    int c0 = (tid & 1) * 64;
    float fsq = g_fsq[m0 + row];
    int lab = label[m0 + row];
    float md = -INFINITY, mn = -INFINITY;
#pragma unroll 4
    for (int j = 0; j < 64; j++) {
        int col = c0 + j;
        float dot = Cs[row * CPITCH + col];
        float d2 = fmaxf(fsq + psq_s[col] - 2.0f * dot, 0.0f);
        float lg = -d2;
        Cs[row * CPITCH + col] = lg;
        md = fmaxf(md, lg);
        if (plab_s[col] == lab) mn = fmaxf(mn, lg);
    }
    float sd = 0.f, sn = 0.f;
#pragma unroll 4
    for (int j = 0; j < 64; j++) {
        int col = c0 + j;
        float lg = Cs[row * CPITCH + col];
        sd += __expf(lg - md);
        if (plab_s[col] == lab) sn += __expf(lg - mn);
    }
    // merge with partner thread (tid ^ 1, same warp)
    float md2 = __shfl_xor_sync(0xffffffffu, md, 1);
    float sd2 = __shfl_xor_sync(0xffffffffu, sd, 1);
    float mn2 = __shfl_xor_sync(0xffffffffu, mn, 1);
    float sn2 = __shfl_xor_sync(0xffffffffu, sn, 1);
    float M = fmaxf(md, md2);
    float SD = sd * __expf(md - M) + sd2 * __expf(md2 - M);
    float Mn = fmaxf(mn, mn2);
    float f0 = (mn == -INFINITY) ? 0.f : __expf(mn - Mn);
    float f1 = (mn2 == -INFINITY) ? 0.f : __expf(mn2 - Mn);
    float SN = sn * f0 + sn2 * f1;
    if ((tid & 1) == 0) {
        size_t o = (size_t)blockIdx.x * B_ROWS + m0 + row;
        g_pmd[o] = M;
        g_psd[o] = SD;
        g_pmn[o] = Mn;
        g_psn[o] = SN;
    }
}

// ===========================================================================
// Kernel 3: combine 32 chunk-partials per row -> loss.
// ===========================================================================
__global__ void combine_kernel(float* __restrict__ out) {
    int r = blockIdx.x * blockDim.x + threadIdx.x;
    if (r >= B_ROWS) return;
    float md = -INFINITY, sd = 0.f, mn = -INFINITY, sn = 0.f;
    for (int c = 0; c < NCHUNK; c++) {
        size_t o = (size_t)c * B_ROWS + r;
        float m2 = g_pmd[o], s2 = g_psd[o];
        float M = fmaxf(md, m2);
        sd = sd * __expf(md - M) + s2 * __expf(m2 - M);
        md = M;
        float mn2 = g_pmn[o], sn2 = g_psn[o];
        float Mn = fmaxf(mn, mn2);
        float f0 = (mn == -INFINITY) ? 0.f : __expf(mn - Mn);
        float f1 = (mn2 == -INFINITY) ? 0.f : __expf(mn2 - Mn);
        sn = sn * f0 + sn2 * f1;
        mn = Mn;
    }
    out[r] = (md + logf(sd)) - (mn + logf(sn));
}

// ===========================================================================
// Launch
// ===========================================================================
extern "C" void kernel_launch(void* const* d_in, const int* in_sizes, int n_in,
                              void* d_out, int out_size) {
    const float* feature = (const float*)d_in[0];
    const int* label = (const int*)d_in[1];
    const float* proto = (const float*)d_in[2];
    const int* plab = (const int*)d_in[3];
    float* out = (float*)d_out;

    cudaFuncSetAttribute(dce_mma_kernel, cudaFuncAttributeMaxDynamicSharedMemorySize,
                         SMEM_TOTAL);

    int warps = B_ROWS + P_ROWS;
    prep_kernel<<<(warps * 32 + 255) / 256, 256>>>(feature, proto);

    dim3 grid(P_ROWS / BN, B_ROWS / BM);
    dce_mma_kernel<<<grid, 256, SMEM_TOTAL>>>(label, plab);

    combine_kernel<<<(B_ROWS + 255) / 256, 256>>>(out);
}

// round 8
// speedup vs baseline: 10.0164x; 1.4114x over previous
#include <cuda_runtime.h>
#include <cuda_fp16.h>
#include <math.h>
#include <stdint.h>

// ===========================================================================
// Problem constants
// ===========================================================================
#define B_ROWS 8192
#define P_ROWS 4096
#define D_DIM  512
#define NCHUNK (P_ROWS / 128)     // 32 column chunks of 128 protos

#define BM 128
#define BN 128
#define KITERS 16                  // 32-k stages
#define NPIPE 4                    // pipeline depth
#define A_STAGE_BYTES 8192         // 128 rows x 64B (32-k of A_hi), SW64 swizzle
#define B_STAGE_BYTES 8192         // 128 rows x 64B (32-k of B_hi), SW64 swizzle
#define STAGE_BYTES (A_STAGE_BYTES + B_STAGE_BYTES)     // 16KB
#define OFF_PSQ  0                 // 128 floats
#define OFF_PLAB 512               // 128 ints
#define OFF_STAGE 1024
#define CPITCH 132                 // epilogue C smem pitch (floats)
#define EPI_BYTES (128 * CPITCH * 4)                     // 67584
#define SMEM_TOTAL (OFF_STAGE + EPI_BYTES)               // 68608 -> 2 CTAs/SM

// ===========================================================================
// Scratch (allocation-free)
// ===========================================================================
__device__ __half g_Ahi[B_ROWS * D_DIM];
__device__ __half g_Bhi[P_ROWS * D_DIM];
__device__ float g_fsq[B_ROWS];
__device__ float g_psq[P_ROWS];
__device__ float g_pmd[NCHUNK * B_ROWS];
__device__ float g_psd[NCHUNK * B_ROWS];
__device__ float g_pmn[NCHUNK * B_ROWS];
__device__ float g_psn[NCHUNK * B_ROWS];

// ===========================================================================
// PTX helpers (base sm_103: cp.async, ldmatrix, mma.sync)
// ===========================================================================
__device__ __forceinline__ uint32_t smem_u32(const void* p) {
    uint32_t a;
    asm("{ .reg .u64 t; cvta.to.shared.u64 t, %1; cvt.u32.u64 %0, t; }" : "=r"(a) : "l"(p));
    return a;
}
__device__ __forceinline__ void cp16(uint32_t dst, const void* src) {
    asm volatile("cp.async.cg.shared.global [%0], [%1], 16;" :: "r"(dst), "l"(src));
}
#define CP_COMMIT() asm volatile("cp.async.commit_group;" ::: "memory")
#define CP_WAIT(n)  asm volatile("cp.async.wait_group %0;" :: "n"(n) : "memory")

#define LDSM_X4(r0, r1, r2, r3, a)                                              \
    asm volatile("ldmatrix.sync.aligned.m8n8.x4.shared.b16 {%0,%1,%2,%3}, [%4];" \
        : "=r"(r0), "=r"(r1), "=r"(r2), "=r"(r3) : "r"(a))

#define MMA16816(c, a, b)                                                       \
    asm volatile("mma.sync.aligned.m16n8k16.row.col.f32.f16.f16.f32 "           \
        "{%0,%1,%2,%3}, {%4,%5,%6,%7}, {%8,%9}, {%0,%1,%2,%3};"                 \
        : "+f"((c)[0]), "+f"((c)[1]), "+f"((c)[2]), "+f"((c)[3])                \
        : "r"((a)[0]), "r"((a)[1]), "r"((a)[2]), "r"((a)[3]),                   \
          "r"((b)[0]), "r"((b)[1]))

// ===========================================================================
// Kernel 1: fp16 quantize + squared norms OF THE QUANTIZED vectors.
// d2 = |f~|^2 + |p~|^2 - 2 f~.p~ = |f~ - p~|^2 exactly: no hi/lo terms needed.
// One warp per row.
// ===========================================================================
__global__ void prep_kernel(const float* __restrict__ feat,
                            const float* __restrict__ proto) {
    int warp = (blockIdx.x * blockDim.x + threadIdx.x) >> 5;
    int lane = threadIdx.x & 31;
    if (warp >= B_ROWS + P_ROWS) return;
    bool isA = warp < B_ROWS;
    int row = isA ? warp : warp - B_ROWS;
    const float* src = (isA ? feat : proto) + (size_t)row * D_DIM;
    __half* dh = (isA ? g_Ahi : g_Bhi) + (size_t)row * D_DIM;

    float s = 0.f;
#pragma unroll
    for (int t = 0; t < 4; t++) {
        int k = t * 128 + lane * 4;
        float4 v = *(const float4*)(src + k);
        __align__(8) __half h[4];
        float x[4] = {v.x, v.y, v.z, v.w};
#pragma unroll
        for (int j = 0; j < 4; j++) {
            h[j] = __float2half_rn(x[j]);
            float hq = __half2float(h[j]);
            s = fmaf(hq, hq, s);           // norm of the QUANTIZED value
        }
        *(uint2*)(dh + k) = *(uint2*)h;
    }
#pragma unroll
    for (int m = 16; m; m >>= 1) s += __shfl_xor_sync(0xffffffffu, s, m);
    if (lane == 0) {
        if (isA) g_fsq[row] = s; else g_psq[row] = s;
    }
}

// ===========================================================================
// Kernel 2: 1-term fp16 mma.sync GEMM (quantized-norm-exact), 4-deep
// cp.async pipeline, + per-CTA dual online LSE partials.
// grid = (32 n-chunks, 64 m-tiles), 256 threads = 2(m) x 4(n) warps.
// Stage (32-k, 16KB): A_hi and B_hi, each 128 rows x 64B, SW64 swizzle
// (c ^ ((r>>1)&3)) -> conflict-free ldmatrix.
// ===========================================================================
__global__ __launch_bounds__(256, 2) void dce_mma_kernel(
    const int* __restrict__ label, const int* __restrict__ plab) {
    extern __shared__ __align__(1024) char smem[];
    float* psq_s = (float*)(smem + OFF_PSQ);
    int* plab_s = (int*)(smem + OFF_PLAB);
    char* stages = smem + OFF_STAGE;
    const uint32_t sb = smem_u32(stages);

    const int tid = threadIdx.x;
    const int lane = tid & 31;
    const int wid = tid >> 5;
    const int wm = wid >> 2;       // 0..1
    const int wn = wid & 3;        // 0..3
    const int m0 = blockIdx.y * BM;
    const int n0 = blockIdx.x * BN;

    if (tid < 128) {
        psq_s[tid] = g_psq[n0 + tid];
        plab_s[tid] = plab[n0 + tid];
    }

    float acc[4][4][4];
#pragma unroll
    for (int i = 0; i < 4; i++)
#pragma unroll
        for (int j = 0; j < 4; j++)
#pragma unroll
            for (int q = 0; q < 4; q++) acc[i][j][q] = 0.f;

    // --- stage loader: 4 x cp.async(16B) per thread (1024 chunks total) ---
    auto issue_stage = [&](int s) {
        uint32_t base = sb + (s & (NPIPE - 1)) * STAGE_BYTES;
        int k0 = s * 32;
        // A_hi: 512 chunks. row r (0..127), chunk c (0..3): k = k0 + c*8
#pragma unroll
        for (int j = 0; j < 2; j++) {
            int idx = tid + j * 256;
            int r = idx >> 2;
            int c = idx & 3;
            uint32_t so = (uint32_t)(r * 64 + ((c ^ ((r >> 1) & 3)) << 4));
            cp16(base + so, g_Ahi + (size_t)(m0 + r) * D_DIM + k0 + c * 8);
        }
        // B_hi: 512 chunks, same layout
#pragma unroll
        for (int j = 0; j < 2; j++) {
            int idx = tid + j * 256;
            int r = idx >> 2;
            int c = idx & 3;
            uint32_t so = (uint32_t)(A_STAGE_BYTES + r * 64 + ((c ^ ((r >> 1) & 3)) << 4));
            cp16(base + so, g_Bhi + (size_t)(n0 + r) * D_DIM + k0 + c * 8);
        }
        CP_COMMIT();
    };

    issue_stage(0);
    issue_stage(1);
    issue_stage(2);

    for (int s = 0; s < KITERS; s++) {
        CP_WAIT(2);                // stage s landed (2 newer groups in flight)
        __syncthreads();           // all warps done reading stage s-1
        if (s + 3 < KITERS) issue_stage(s + 3);

        uint32_t base = sb + (s & (NPIPE - 1)) * STAGE_BYTES;
        uint32_t baseB = base + A_STAGE_BYTES;
#pragma unroll
        for (int ks = 0; ks < 2; ks++) {
            // B fragments for this k-16 slice
            uint32_t Bh[4][2];
#pragma unroll
            for (int p = 0; p < 2; p++) {
                int rn = wn * 32 + p * 16 + ((lane >> 4) << 3) + (lane & 7);
                int ch = ks * 2 + ((lane >> 3) & 1);
                uint32_t bh = baseB + rn * 64 + ((ch ^ ((rn >> 1) & 3)) << 4);
                LDSM_X4(Bh[2 * p][0], Bh[2 * p][1], Bh[2 * p + 1][0], Bh[2 * p + 1][1], bh);
            }
            // A_hi fragments per mt
#pragma unroll
            for (int mt = 0; mt < 4; mt++) {
                uint32_t Ah[4];
                int row = wm * 64 + mt * 16 + (lane & 15);
                int ch = ks * 2 + (lane >> 4);
                uint32_t ah = base + row * 64 + ((ch ^ ((row >> 1) & 3)) << 4);
                LDSM_X4(Ah[0], Ah[1], Ah[2], Ah[3], ah);
#pragma unroll
                for (int nt = 0; nt < 4; nt++) {
                    MMA16816(acc[mt][nt], Ah, Bh[nt]);
                }
            }
        }
    }

    CP_WAIT(0);
    __syncthreads();

    // --- dump accumulators to SMEM (reuse stage memory) ---
    float* Cs = (float*)stages;
#pragma unroll
    for (int mt = 0; mt < 4; mt++)
#pragma unroll
        for (int nt = 0; nt < 4; nt++) {
            int r = wm * 64 + mt * 16 + (lane >> 2);
            int c = wn * 32 + nt * 8 + ((lane & 3) << 1);
            Cs[r * CPITCH + c] = acc[mt][nt][0];
            Cs[r * CPITCH + c + 1] = acc[mt][nt][1];
            Cs[(r + 8) * CPITCH + c] = acc[mt][nt][2];
            Cs[(r + 8) * CPITCH + c + 1] = acc[mt][nt][3];
        }
    __syncthreads();

    // --- per-thread dual online LSE over 64 cols, pair-merge, write partials
    int row = tid >> 1;
    int c0 = (tid & 1) * 64;
    float fsq = g_fsq[m0 + row];
    int lab = label[m0 + row];
    float md = -INFINITY, mn = -INFINITY;
#pragma unroll 4
    for (int j = 0; j < 64; j++) {
        int col = c0 + j;
        float dot = Cs[row * CPITCH + col];
        float d2 = fmaxf(fsq + psq_s[col] - 2.0f * dot, 0.0f);
        float lg = -d2;
        Cs[row * CPITCH + col] = lg;
        md = fmaxf(md, lg);
        if (plab_s[col] == lab) mn = fmaxf(mn, lg);
    }
    float sd = 0.f, sn = 0.f;
#pragma unroll 4
    for (int j = 0; j < 64; j++) {
        int col = c0 + j;
        float lg = Cs[row * CPITCH + col];
        sd += __expf(lg - md);
        if (plab_s[col] == lab) sn += __expf(lg - mn);
    }
    // merge with partner thread (tid ^ 1, same warp)
    float md2 = __shfl_xor_sync(0xffffffffu, md, 1);
    float sd2 = __shfl_xor_sync(0xffffffffu, sd, 1);
    float mn2 = __shfl_xor_sync(0xffffffffu, mn, 1);
    float sn2 = __shfl_xor_sync(0xffffffffu, sn, 1);
    float M = fmaxf(md, md2);
    float SD = sd * __expf(md - M) + sd2 * __expf(md2 - M);
    float Mn = fmaxf(mn, mn2);
    float f0 = (mn == -INFINITY) ? 0.f : __expf(mn - Mn);
    float f1 = (mn2 == -INFINITY) ? 0.f : __expf(mn2 - Mn);
    float SN = sn * f0 + sn2 * f1;
    if ((tid & 1) == 0) {
        size_t o = (size_t)blockIdx.x * B_ROWS + m0 + row;
        g_pmd[o] = M;
        g_psd[o] = SD;
        g_pmn[o] = Mn;
        g_psn[o] = SN;
    }
}

// ===========================================================================
// Kernel 3: combine 32 chunk-partials per row -> loss.
// ===========================================================================
__global__ void combine_kernel(float* __restrict__ out) {
    int r = blockIdx.x * blockDim.x + threadIdx.x;
    if (r >= B_ROWS) return;
    float md = -INFINITY, sd = 0.f, mn = -INFINITY, sn = 0.f;
    for (int c = 0; c < NCHUNK; c++) {
        size_t o = (size_t)c * B_ROWS + r;
        float m2 = g_pmd[o], s2 = g_psd[o];
        float M = fmaxf(md, m2);
        sd = sd * __expf(md - M) + s2 * __expf(m2 - M);
        md = M;
        float mn2 = g_pmn[o], sn2 = g_psn[o];
        float Mn = fmaxf(mn, mn2);
        float f0 = (mn == -INFINITY) ? 0.f : __expf(mn - Mn);
        float f1 = (mn2 == -INFINITY) ? 0.f : __expf(mn2 - Mn);
        sn = sn * f0 + sn2 * f1;
        mn = Mn;
    }
    out[r] = (md + logf(sd)) - (mn + logf(sn));
}

// ===========================================================================
// Launch
// ===========================================================================
extern "C" void kernel_launch(void* const* d_in, const int* in_sizes, int n_in,
                              void* d_out, int out_size) {
    const float* feature = (const float*)d_in[0];
    const int* label = (const int*)d_in[1];
    const float* proto = (const float*)d_in[2];
    const int* plab = (const int*)d_in[3];
    float* out = (float*)d_out;

    cudaFuncSetAttribute(dce_mma_kernel, cudaFuncAttributeMaxDynamicSharedMemorySize,
                         SMEM_TOTAL);

    int warps = B_ROWS + P_ROWS;
    prep_kernel<<<(warps * 32 + 255) / 256, 256>>>(feature, proto);

    dim3 grid(P_ROWS / BN, B_ROWS / BM);
    dce_mma_kernel<<<grid, 256, SMEM_TOTAL>>>(label, plab);

    combine_kernel<<<(B_ROWS + 255) / 256, 256>>>(out);
}